// round 15
// baseline (speedup 1.0000x reference)
#include <cuda_runtime.h>
#include <cuda_bf16.h>
#include <math.h>
#include <stdint.h>

#define DIN 1546
#define DH  128
#define DFF 512
#define NL  2

static const int NMAXC = 20000;
static const int EMAXC = 640000;

// ---------------- scratch (device globals; no allocation allowed) ----------
__device__ __align__(16) float g_qkv  [NMAXC * 6 * DH];
__device__ __align__(16) float g_scr  [EMAXC];
__device__ __align__(16) float g_ss   [NMAXC * DH];
__device__ __align__(16) float g_t    [NMAXC * DFF];
__device__ __align__(16) float g_h2   [NMAXC * DH];
__device__ __align__(16) float g_wpack[NL * DIN * 6 * DH];
__device__ __align__(16) float g_bpack[NL * 6 * DH];
__device__ __align__(16) float g_wc1  [DH * 6 * DH];
__device__ __align__(16) float g_wc2  [DH * DH];
__device__ __align__(16) float g_bc1  [6 * DH];
__device__ __align__(16) float g_bc2  [DH];
__device__ int g_src[EMAXC];
__device__ int g_dst[EMAXC];
__device__ int g_eidx[EMAXC];
__device__ int g_rowptr[NMAXC + 1];
__device__ int g_cnt[NMAXC];
__device__ int g_cur[NMAXC];
__device__ double g_Zd[NL];
__device__ int    g_is64;

// ---------------- bf16 split helpers ----------------------------------------
__device__ __forceinline__ uint32_t pack_bf2(__nv_bfloat16 a, __nv_bfloat16 b) {
    __nv_bfloat162 t = __halves2bfloat162(a, b);
    return *reinterpret_cast<uint32_t*>(&t);
}
__device__ __forceinline__ void split2(float x0, float x1, uint32_t& h, uint32_t& l) {
    __nv_bfloat16 h0 = __float2bfloat16(x0);
    __nv_bfloat16 h1 = __float2bfloat16(x1);
    __nv_bfloat16 l0 = __float2bfloat16(x0 - __bfloat162float(h0));
    __nv_bfloat16 l1 = __float2bfloat16(x1 - __bfloat162float(h1));
    h = pack_bf2(h0, h1);
    l = pack_bf2(l0, l1);
}
__device__ __forceinline__ void mma_bf16(float* c, const uint32_t* a, const uint32_t* b) {
    asm volatile(
        "mma.sync.aligned.m16n8k16.row.col.f32.bf16.bf16.f32 "
        "{%0,%1,%2,%3},{%4,%5,%6,%7},{%8,%9},{%0,%1,%2,%3};"
        : "+f"(c[0]), "+f"(c[1]), "+f"(c[2]), "+f"(c[3])
        : "r"(a[0]), "r"(a[1]), "r"(a[2]), "r"(a[3]), "r"(b[0]), "r"(b[1]));
}

// ---------------- edge-index dtype probe + decode ---------------------------
__global__ void detect_idx_k(const int* __restrict__ raw, int nsamp)
{
    int i = blockIdx.x * blockDim.x + threadIdx.x;
    if (i < nsamp && raw[2 * i + 1] != 0) atomicExch(&g_is64, 0);
}

__global__ void decode_idx_k(int E, int N, const int* __restrict__ raw,
                             int* __restrict__ src, int* __restrict__ dst)
{
    int is64 = g_is64;
    for (int e = blockIdx.x * blockDim.x + threadIdx.x; e < E;
         e += gridDim.x * blockDim.x) {
        int s, d;
        if (is64) {
            s = raw[2 * (size_t)e];
            d = raw[2 * ((size_t)E + e)];
        } else {
            s = raw[e];
            d = raw[(size_t)E + e];
        }
        src[e] = min(max(s, 0), N - 1);
        dst[e] = min(max(d, 0), N - 1);
    }
}

// ---------------- CSR build ---------------------------------------------------
__global__ void hist_k(int E, const int* __restrict__ dst, int* __restrict__ cnt)
{
    for (int e = blockIdx.x * blockDim.x + threadIdx.x; e < E;
         e += gridDim.x * blockDim.x)
        atomicAdd(&cnt[dst[e]], 1);
}

__global__ void scan_k(int N, const int* __restrict__ cnt,
                       int* __restrict__ rowptr, int* __restrict__ cur)
{
    __shared__ int part[1024];
    int t = threadIdx.x;
    int chunk = (N + 1023) / 1024;
    int lo = t * chunk, hi = min(lo + chunk, N);
    int s = 0;
    for (int j = lo; j < hi; j++) s += cnt[j];
    part[t] = s;
    __syncthreads();
    for (int off = 1; off < 1024; off <<= 1) {
        int v = (t >= off) ? part[t - off] : 0;
        __syncthreads();
        part[t] += v;
        __syncthreads();
    }
    int run = (t == 0) ? 0 : part[t - 1];
    for (int j = lo; j < hi; j++) {
        rowptr[j] = run;
        cur[j] = run;
        run += cnt[j];
    }
    if (t == 1023) rowptr[N] = part[1023];
}

__global__ void scatter_k(int E, const int* __restrict__ dst,
                          int* __restrict__ cur, int* __restrict__ eidx)
{
    for (int e = blockIdx.x * blockDim.x + threadIdx.x; e < E;
         e += gridDim.x * blockDim.x) {
        int pos = atomicAdd(&cur[dst[e]], 1);
        eidx[pos] = e;
    }
}

// ---------------- weight/bias packing (coalesced both sides) -----------------
__global__ void pack_w_k(const float* __restrict__ Wq, const float* __restrict__ Wk,
                         const float* __restrict__ Wv, const float* __restrict__ Wr,
                         const float* __restrict__ Whi, const float* __restrict__ Whj,
                         float* __restrict__ out)
{
    const float* Ws[6] = {Wq, Wk, Wv, Wr, Whi, Whj};
    size_t total = (size_t)NL * DIN * 768;
    for (size_t i = blockIdx.x * (size_t)blockDim.x + threadIdx.x; i < total;
         i += (size_t)gridDim.x * blockDim.x) {
        int n = i % 768;
        int k = (i / 768) % DIN;
        int l = i / ((size_t)768 * DIN);
        int j = n >> 7, c = n & 127;
        out[i] = Ws[j][(size_t)l * DIN * DH + (size_t)k * DH + c];
    }
}

__global__ void pack_b_k(const float* __restrict__ bq, const float* __restrict__ bk,
                         const float* __restrict__ bv, const float* __restrict__ br,
                         float* __restrict__ out)
{
    int i = threadIdx.x + blockIdx.x * blockDim.x;
    if (i >= NL * 768) return;
    int c = i % 768, l = i / 768;
    int j = c / DH, cc = c % DH;
    float v = 0.f;
    if (j == 0) v = bq[l * DH + cc];
    else if (j == 1) v = bk[l * DH + cc];
    else if (j == 2) v = bv[l * DH + cc];
    else if (j == 3) v = br[l * DH + cc];
    out[i] = v;
}

// ---------------- weight composition ------------------------------------------
__global__ void compose_w_k(const float* __restrict__ A, const float* __restrict__ B,
                            float* __restrict__ Cw, int No, int K)
{
    __shared__ float sA[128][65];
    const int tid = threadIdx.x;
    const int n    = tid & 63;
    const int mset = tid >> 6;
    const int nt0 = blockIdx.x * 64;
    const int k0  = blockIdx.y * 64;
    const int klen = min(64, K - k0);

    for (int id = tid; id < 128 * 64; id += 256) {
        int m = id >> 6, kk = id & 63;
        sA[m][kk] = (kk < klen) ? A[(size_t)m * K + k0 + kk] : 0.f;
    }
    __syncthreads();

    float acc[32];
#pragma unroll
    for (int i = 0; i < 32; i++) acc[i] = 0.f;

    for (int kk = 0; kk < klen; kk++) {
        float b = B[(size_t)(k0 + kk) * No + nt0 + n];
#pragma unroll
        for (int i = 0; i < 32; i++)
            acc[i] += sA[mset * 32 + i][kk] * b;
    }
#pragma unroll
    for (int i = 0; i < 32; i++)
        atomicAdd(&Cw[(size_t)(mset * 32 + i) * No + nt0 + n], acc[i]);
}

__global__ void compose_b_k(const float* __restrict__ lb, const float* __restrict__ B,
                            const float* __restrict__ badd, float* __restrict__ out,
                            int No, int K)
{
    int n = blockIdx.x * blockDim.x + threadIdx.x;
    if (n >= No) return;
    float s = badd ? badd[n] : 0.f;
    for (int k = 0; k < K; k++)
        s += lb[k] * B[(size_t)k * No + n];
    out[n] = s;
}

// ---------------- BM=256 tensor GEMM (proven; l0 proj K=1546) ----------------
__global__ void __launch_bounds__(256, 1)
mma_gemm_k(int M, int Nn, int K,
           const float* __restrict__ A, int lda,
           const float* __restrict__ B, int ldb,
           const float* __restrict__ bias,
           float* __restrict__ C, int ldc, int act)
{
    __shared__ __align__(16) uint32_t Asf[2][2][16][32][4];
    __shared__ __align__(16) uint32_t Bsf[2][2][16][32][2];

    const int tid  = threadIdx.x;
    const int lane = tid & 31;
    const int wid  = tid >> 5;
    const int g    = lane >> 2;
    const int tig  = lane & 3;
    const int warp_m = wid & 3;
    const int warp_n = wid >> 2;
    const int row0 = blockIdx.y * 256;
    const int col0 = blockIdx.x * 128;

    float acc[4][8][4];
#pragma unroll
    for (int m = 0; m < 4; m++)
#pragma unroll
        for (int n = 0; n < 8; n++)
#pragma unroll
            for (int r = 0; r < 4; r++) acc[m][n][r] = 0.f;

    float pa[2][8], pb[2][4];

    auto load_regs = [&](int k0) {
#pragma unroll
        for (int i = 0; i < 2; i++) {
            int mt = wid * 2 + i;
#pragma unroll
            for (int r = 0; r < 4; r++) {
                int rr = row0 + mt * 16 + g + 8 * (r & 1);
                int c0 = k0 + 2 * tig + 8 * (r >> 1);
                bool rok = rr < M;
                const float* Ap = A + (size_t)rr * lda + c0;
                pa[i][r * 2 + 0] = (rok && c0 < K)     ? Ap[0] : 0.f;
                pa[i][r * 2 + 1] = (rok && c0 + 1 < K) ? Ap[1] : 0.f;
            }
        }
#pragma unroll
        for (int i = 0; i < 2; i++) {
            int nt = wid * 2 + i;
            int cc = col0 + nt * 8 + g;
            bool cok = cc < Nn;
#pragma unroll
            for (int r = 0; r < 2; r++) {
                int kk = k0 + 2 * tig + 8 * r;
                pb[i][r * 2 + 0] = (cok && kk < K)     ? B[(size_t)kk * ldb + cc] : 0.f;
                pb[i][r * 2 + 1] = (cok && kk + 1 < K) ? B[(size_t)(kk + 1) * ldb + cc] : 0.f;
            }
        }
    };

    auto store_smem = [&](int buf) {
#pragma unroll
        for (int i = 0; i < 2; i++) {
            int mt = wid * 2 + i;
            uint4 h, l;
            split2(pa[i][0], pa[i][1], h.x, l.x);
            split2(pa[i][2], pa[i][3], h.y, l.y);
            split2(pa[i][4], pa[i][5], h.z, l.z);
            split2(pa[i][6], pa[i][7], h.w, l.w);
            *(uint4*)&Asf[buf][0][mt][lane][0] = h;
            *(uint4*)&Asf[buf][1][mt][lane][0] = l;
        }
#pragma unroll
        for (int i = 0; i < 2; i++) {
            int nt = wid * 2 + i;
            uint2 h, l;
            split2(pb[i][0], pb[i][1], h.x, l.x);
            split2(pb[i][2], pb[i][3], h.y, l.y);
            *(uint2*)&Bsf[buf][0][nt][lane][0] = h;
            *(uint2*)&Bsf[buf][1][nt][lane][0] = l;
        }
    };

    auto compute = [&](int buf) {
        uint32_t ah[4][4], al[4][4];
#pragma unroll
        for (int m = 0; m < 4; m++) {
            int mt = warp_m * 4 + m;
            uint4 t = *(const uint4*)&Asf[buf][0][mt][lane][0];
            ah[m][0] = t.x; ah[m][1] = t.y; ah[m][2] = t.z; ah[m][3] = t.w;
            uint4 u = *(const uint4*)&Asf[buf][1][mt][lane][0];
            al[m][0] = u.x; al[m][1] = u.y; al[m][2] = u.z; al[m][3] = u.w;
        }
#pragma unroll
        for (int n = 0; n < 8; n++) {
            int nt = warp_n * 8 + n;
            uint32_t bh[2], bl[2];
            uint2 t = *(const uint2*)&Bsf[buf][0][nt][lane][0];
            bh[0] = t.x; bh[1] = t.y;
            uint2 u = *(const uint2*)&Bsf[buf][1][nt][lane][0];
            bl[0] = u.x; bl[1] = u.y;
#pragma unroll
            for (int m = 0; m < 4; m++) {
                mma_bf16(acc[m][n], ah[m], bh);
                mma_bf16(acc[m][n], ah[m], bl);
                mma_bf16(acc[m][n], al[m], bh);
            }
        }
    };

    load_regs(0);
    store_smem(0);
    __syncthreads();

    int buf = 0;
    for (int k0 = 0; k0 < K; k0 += 16) {
        int kn = k0 + 16;
        bool more = kn < K;
        if (more) load_regs(kn);
        compute(buf);
        if (more) {
            store_smem(buf ^ 1);
            __syncthreads();
            buf ^= 1;
        }
    }

#pragma unroll
    for (int m = 0; m < 4; m++) {
        int rb = row0 + warp_m * 64 + m * 16 + g;
#pragma unroll
        for (int n = 0; n < 8; n++) {
            int cb = col0 + warp_n * 64 + n * 8 + tig * 2;
#pragma unroll
            for (int h = 0; h < 2; h++) {
                int rr = rb + h * 8;
                if (rr >= M) continue;
#pragma unroll
                for (int q = 0; q < 2; q++) {
                    int cc = cb + q;
                    if (cc >= Nn) continue;
                    float v = acc[m][n][h * 2 + q] + (bias ? bias[cc] : 0.f);
                    if (act == 1) v = fmaxf(v, 0.f);
                    else if (act == 2) v = v > 0.f ? v : 0.01f * v;
                    C[(size_t)rr * ldc + cc] = v;
                }
            }
        }
    }
}

// ---------------- BM=128 tensor GEMM, optional fused residual-LN epilogue ----
__global__ void __launch_bounds__(256, 1)
bm128_gemm_k(int M, int Nn, int K,
             const float* __restrict__ A, int lda,
             const float* __restrict__ B, int ldb,
             const float* __restrict__ bias,
             float* __restrict__ C, int ldc, int act,
             const float* __restrict__ lnres,
             const float* __restrict__ gam, const float* __restrict__ bet)
{
    __shared__ __align__(16) uint32_t Asf[2][2][8][32][4];
    __shared__ __align__(16) uint32_t Bsf[2][2][16][32][2];
    __shared__ float pS[2][128], pS2[2][128];

    const int tid  = threadIdx.x;
    const int lane = tid & 31;
    const int wid  = tid >> 5;
    const int g    = lane >> 2;
    const int tig  = lane & 3;
    const int warp_m = wid & 3;
    const int warp_n = wid >> 2;
    const int row0 = blockIdx.y * 128;
    const int col0 = blockIdx.x * 128;

    float acc[2][8][4];
#pragma unroll
    for (int m = 0; m < 2; m++)
#pragma unroll
        for (int n = 0; n < 8; n++)
#pragma unroll
            for (int r = 0; r < 4; r++) acc[m][n][r] = 0.f;

    float pa[8], pb[2][4];

    auto load_regs = [&](int k0) {
#pragma unroll
        for (int r = 0; r < 4; r++) {
            int rr = row0 + wid * 16 + g + 8 * (r & 1);
            int c0 = k0 + 2 * tig + 8 * (r >> 1);
            bool rok = rr < M;
            const float* Ap = A + (size_t)rr * lda + c0;
            pa[r * 2 + 0] = (rok && c0 < K)     ? Ap[0] : 0.f;
            pa[r * 2 + 1] = (rok && c0 + 1 < K) ? Ap[1] : 0.f;
        }
#pragma unroll
        for (int i = 0; i < 2; i++) {
            int nt = wid * 2 + i;
            int cc = col0 + nt * 8 + g;
            bool cok = cc < Nn;
#pragma unroll
            for (int r = 0; r < 2; r++) {
                int kk = k0 + 2 * tig + 8 * r;
                pb[i][r * 2 + 0] = (cok && kk < K)     ? B[(size_t)kk * ldb + cc] : 0.f;
                pb[i][r * 2 + 1] = (cok && kk + 1 < K) ? B[(size_t)(kk + 1) * ldb + cc] : 0.f;
            }
        }
    };

    auto store_smem = [&](int buf) {
        uint4 h, l;
        split2(pa[0], pa[1], h.x, l.x);
        split2(pa[2], pa[3], h.y, l.y);
        split2(pa[4], pa[5], h.z, l.z);
        split2(pa[6], pa[7], h.w, l.w);
        *(uint4*)&Asf[buf][0][wid][lane][0] = h;
        *(uint4*)&Asf[buf][1][wid][lane][0] = l;
#pragma unroll
        for (int i = 0; i < 2; i++) {
            int nt = wid * 2 + i;
            uint2 bh, bl;
            split2(pb[i][0], pb[i][1], bh.x, bl.x);
            split2(pb[i][2], pb[i][3], bh.y, bl.y);
            *(uint2*)&Bsf[buf][0][nt][lane][0] = bh;
            *(uint2*)&Bsf[buf][1][nt][lane][0] = bl;
        }
    };

    auto compute = [&](int buf) {
        uint32_t ah[2][4], al[2][4];
#pragma unroll
        for (int m = 0; m < 2; m++) {
            int mt = warp_m * 2 + m;
            uint4 t = *(const uint4*)&Asf[buf][0][mt][lane][0];
            ah[m][0] = t.x; ah[m][1] = t.y; ah[m][2] = t.z; ah[m][3] = t.w;
            uint4 u = *(const uint4*)&Asf[buf][1][mt][lane][0];
            al[m][0] = u.x; al[m][1] = u.y; al[m][2] = u.z; al[m][3] = u.w;
        }
#pragma unroll
        for (int n = 0; n < 8; n++) {
            int nt = warp_n * 8 + n;
            uint32_t bh[2], bl[2];
            uint2 t = *(const uint2*)&Bsf[buf][0][nt][lane][0];
            bh[0] = t.x; bh[1] = t.y;
            uint2 u = *(const uint2*)&Bsf[buf][1][nt][lane][0];
            bl[0] = u.x; bl[1] = u.y;
#pragma unroll
            for (int m = 0; m < 2; m++) {
                mma_bf16(acc[m][n], ah[m], bh);
                mma_bf16(acc[m][n], ah[m], bl);
                mma_bf16(acc[m][n], al[m], bh);
            }
        }
    };

    load_regs(0);
    store_smem(0);
    __syncthreads();

    int buf = 0;
    for (int k0 = 0; k0 < K; k0 += 16) {
        int kn = k0 + 16;
        bool more = kn < K;
        if (more) load_regs(kn);
        compute(buf);
        if (more) {
            store_smem(buf ^ 1);
            __syncthreads();
            buf ^= 1;
        }
    }

    if (gam == nullptr) {
#pragma unroll
        for (int m = 0; m < 2; m++) {
            int rb = row0 + warp_m * 32 + m * 16 + g;
#pragma unroll
            for (int n = 0; n < 8; n++) {
                int cb = col0 + warp_n * 64 + n * 8 + tig * 2;
#pragma unroll
                for (int h = 0; h < 2; h++) {
                    int rr = rb + h * 8;
                    if (rr >= M) continue;
#pragma unroll
                    for (int q = 0; q < 2; q++) {
                        int cc = cb + q;
                        if (cc >= Nn) continue;
                        float v = acc[m][n][h * 2 + q] + (bias ? bias[cc] : 0.f);
                        if (act == 1) v = fmaxf(v, 0.f);
                        else if (act == 2) v = v > 0.f ? v : 0.01f * v;
                        C[(size_t)rr * ldc + cc] = v;
                    }
                }
            }
        }
        return;
    }

    // fused residual-LN epilogue (Nn==128, col0==0)
    __syncthreads();
#pragma unroll
    for (int m = 0; m < 2; m++) {
#pragma unroll
        for (int h = 0; h < 2; h++) {
            int lrow = warp_m * 32 + m * 16 + g + 8 * h;
            int row  = row0 + lrow;
            bool rok = row < M;
            float rs = 0.f, rs2 = 0.f;
#pragma unroll
            for (int n = 0; n < 8; n++) {
#pragma unroll
                for (int q = 0; q < 2; q++) {
                    int col = warp_n * 64 + n * 8 + tig * 2 + q;
                    float v = acc[m][n][h * 2 + q] + bias[col]
                            + (rok ? lnres[(size_t)row * 128 + col] : 0.f);
                    rs += v; rs2 += v * v;
                }
            }
            rs  += __shfl_xor_sync(0xffffffffu, rs, 1);
            rs  += __shfl_xor_sync(0xffffffffu, rs, 2);
            rs2 += __shfl_xor_sync(0xffffffffu, rs2, 1);
            rs2 += __shfl_xor_sync(0xffffffffu, rs2, 2);
            if (tig == 0) { pS[warp_n][lrow] = rs; pS2[warp_n][lrow] = rs2; }
        }
    }
    __syncthreads();
#pragma unroll
    for (int m = 0; m < 2; m++) {
#pragma unroll
        for (int h = 0; h < 2; h++) {
            int lrow = warp_m * 32 + m * 16 + g + 8 * h;
            int row  = row0 + lrow;
            if (row >= M) continue;
            float ts  = pS[0][lrow] + pS[1][lrow];
            float ts2 = pS2[0][lrow] + pS2[1][lrow];
            float mean = ts * (1.f / 128.f);
            float var  = ts2 * (1.f / 128.f) - mean * mean;
            float rstd = rsqrtf(var + 1e-5f);
#pragma unroll
            for (int n = 0; n < 8; n++) {
#pragma unroll
                for (int q = 0; q < 2; q++) {
                    int col = warp_n * 64 + n * 8 + tig * 2 + q;
                    float v = acc[m][n][h * 2 + q] + bias[col]
                            + lnres[(size_t)row * 128 + col];
                    C[(size_t)row * ldc + col] = (v - mean) * rstd * gam[col] + bet[col];
                }
            }
        }
    }
}

// ---------------- edge pass: score + double-precision Z (no max pass) --------
__global__ void edge_score_k(int E, const int* __restrict__ srcA,
                             const int* __restrict__ dstA,
                             const float* __restrict__ qkv,
                             float* __restrict__ score,
                             double* __restrict__ Zd)
{
    int warp  = (blockIdx.x * blockDim.x + threadIdx.x) >> 5;
    int lane  = threadIdx.x & 31;
    int wloc  = threadIdx.x >> 5;
    __shared__ float sm[8];
    float d = 0.f;
    bool valid = warp < E;
    if (valid) {
        int src = srcA[warp];
        int dst = dstA[warp];
        float4 q = *(const float4*)(qkv + (size_t)dst * 768 + lane * 4);
        float4 k = *(const float4*)(qkv + (size_t)src * 768 + 128 + lane * 4);
        d = q.x * k.x + q.y * k.y + q.z * k.z + q.w * k.w;
#pragma unroll
        for (int o = 16; o; o >>= 1) d += __shfl_xor_sync(0xffffffffu, d, o);
        if (lane == 0) score[warp] = d;
    }
    if (lane == 0) sm[wloc] = valid ? d : 0.f;
    // mark invalid warps with -inf sentinel via separate flag array in smem
    __shared__ int vl[8];
    if (lane == 0) vl[wloc] = valid ? 1 : 0;
    __syncthreads();
    if (threadIdx.x == 0) {
        double z = 0.0;
        int nw = blockDim.x >> 5;
        for (int i = 0; i < nw; i++)
            if (vl[i]) z += exp((double)sm[i]);
        atomicAdd(Zd, z);
    }
}

// ---------------- fused aggregate + LN1 (fast-math sigmoid, inline softmax) --
__global__ void __launch_bounds__(128)
aggr_ln1_k(const int* __restrict__ rowptr, const int* __restrict__ eidx,
           const int* __restrict__ srcA,
           const float* __restrict__ qkv, const float* __restrict__ eattr,
           const float* __restrict__ score,
           const double* __restrict__ Zd,
           const float* __restrict__ gam, const float* __restrict__ bet,
           float* __restrict__ out)
{
    int n = blockIdx.x, d = threadIdx.x;
    int beg = rowptr[n], end = rowptr[n + 1];
    float hj = qkv[(size_t)n * 768 + 640 + d];
    float lnZ = (float)log(*Zd);
    float acc = 0.f;

    int i = beg;
    for (; i + 3 < end; i += 4) {
        int e0 = eidx[i], e1 = eidx[i + 1], e2 = eidx[i + 2], e3 = eidx[i + 3];
        int s0 = srcA[e0], s1 = srcA[e1], s2 = srcA[e2], s3 = srcA[e3];
        float p0 = __expf(__ldg(score + e0) - lnZ);
        float p1 = __expf(__ldg(score + e1) - lnZ);
        float p2 = __expf(__ldg(score + e2) - lnZ);
        float p3 = __expf(__ldg(score + e3) - lnZ);
        float v0  = qkv[(size_t)s0 * 768 + 256 + d];
        float v1  = qkv[(size_t)s1 * 768 + 256 + d];
        float v2  = qkv[(size_t)s2 * 768 + 256 + d];
        float v3  = qkv[(size_t)s3 * 768 + 256 + d];
        float hi0 = qkv[(size_t)s0 * 768 + 512 + d];
        float hi1 = qkv[(size_t)s1 * 768 + 512 + d];
        float hi2 = qkv[(size_t)s2 * 768 + 512 + d];
        float hi3 = qkv[(size_t)s3 * 768 + 512 + d];
        float ea0 = eattr[(size_t)e0 * 128 + d];
        float ea1 = eattr[(size_t)e1 * 128 + d];
        float ea2 = eattr[(size_t)e2 * 128 + d];
        float ea3 = eattr[(size_t)e3 * 128 + d];
        acc += p0 * v0 * __fdividef(1.f, 1.f + __expf(-(ea0 + hi0 + hj)));
        acc += p1 * v1 * __fdividef(1.f, 1.f + __expf(-(ea1 + hi1 + hj)));
        acc += p2 * v2 * __fdividef(1.f, 1.f + __expf(-(ea2 + hi2 + hj)));
        acc += p3 * v3 * __fdividef(1.f, 1.f + __expf(-(ea3 + hi3 + hj)));
    }
    for (; i < end; i++) {
        int e0 = eidx[i];
        int s0 = srcA[e0];
        float p0 = __expf(__ldg(score + e0) - lnZ);
        float v0  = qkv[(size_t)s0 * 768 + 256 + d];
        float hi0 = qkv[(size_t)s0 * 768 + 512 + d];
        float ea0 = eattr[(size_t)e0 * 128 + d];
        acc += p0 * v0 * __fdividef(1.f, 1.f + __expf(-(ea0 + hi0 + hj)));
    }

    float h = acc + qkv[(size_t)n * 768 + 384 + d];

    float s = h, s2 = h * h;
#pragma unroll
    for (int o = 16; o; o >>= 1) {
        s  += __shfl_xor_sync(0xffffffffu, s, o);
        s2 += __shfl_xor_sync(0xffffffffu, s2, o);
    }
    __shared__ float sm[8];
    int w = threadIdx.x >> 5, l = threadIdx.x & 31;
    if (l == 0) { sm[w] = s; sm[4 + w] = s2; }
    __syncthreads();
    float ts  = sm[0] + sm[1] + sm[2] + sm[3];
    float ts2 = sm[4] + sm[5] + sm[6] + sm[7];
    float mean = ts * (1.f / 128.f);
    float var  = ts2 * (1.f / 128.f) - mean * mean;
    out[(size_t)n * 128 + d] = (h - mean) * rsqrtf(var + 1e-5f) * gam[d] + bet[d];
}

// ---------------- host-side persistent stream/events -------------------------
static cudaStream_t g_s2 = nullptr;
static cudaEvent_t  g_evF = nullptr, g_evJ = nullptr;

// ---------------- host orchestration ---------------------------------------
extern "C" void kernel_launch(void* const* d_in, const int* in_sizes, int n_in,
                              void* d_out, int out_size)
{
    const float* x_in  = (const float*)d_in[0];
    const int*   eiraw = (const int*)d_in[1];
    const float* eattr = (const float*)d_in[2];
    const float* Wq  = (const float*)d_in[3];
    const float* bq  = (const float*)d_in[4];
    const float* Wk  = (const float*)d_in[5];
    const float* bk  = (const float*)d_in[6];
    const float* Wv  = (const float*)d_in[7];
    const float* bv  = (const float*)d_in[8];
    const float* Wr  = (const float*)d_in[9];
    const float* br  = (const float*)d_in[10];
    const float* Whi = (const float*)d_in[11];
    const float* Whj = (const float*)d_in[12];
    const float* W1  = (const float*)d_in[13];
    const float* b1  = (const float*)d_in[14];
    const float* W2  = (const float*)d_in[15];
    const float* b2  = (const float*)d_in[16];
    const float* g1  = (const float*)d_in[17];
    const float* be1 = (const float*)d_in[18];
    const float* g2  = (const float*)d_in[19];
    const float* be2 = (const float*)d_in[20];
    const float* linW  = (const float*)d_in[21];
    const float* linb  = (const float*)d_in[22];
    const float* lin2W = (const float*)d_in[23];
    const float* lin2b = (const float*)d_in[24];

    const int N = in_sizes[0] / DIN;
    const int E = in_sizes[1] / 2;

    if (!g_s2) {
        cudaStreamCreateWithFlags(&g_s2, cudaStreamNonBlocking);
        cudaEventCreateWithFlags(&g_evF, cudaEventDisableTiming);
        cudaEventCreateWithFlags(&g_evJ, cudaEventDisableTiming);
    }

    float *qkv, *score, *ss, *tbuf, *h2, *wpack, *bpack;
    float *wc1, *wc2, *bc1, *bc2;
    double* Zd;
    int *srcA, *dstA, *eidx, *rowptr, *cnt, *cur;
    void* p;
    cudaGetSymbolAddress(&p, g_qkv);    qkv    = (float*)p;
    cudaGetSymbolAddress(&p, g_scr);    score  = (float*)p;
    cudaGetSymbolAddress(&p, g_ss);     ss     = (float*)p;
    cudaGetSymbolAddress(&p, g_t);      tbuf   = (float*)p;
    cudaGetSymbolAddress(&p, g_h2);     h2     = (float*)p;
    cudaGetSymbolAddress(&p, g_wpack);  wpack  = (float*)p;
    cudaGetSymbolAddress(&p, g_bpack);  bpack  = (float*)p;
    cudaGetSymbolAddress(&p, g_wc1);    wc1    = (float*)p;
    cudaGetSymbolAddress(&p, g_wc2);    wc2    = (float*)p;
    cudaGetSymbolAddress(&p, g_bc1);    bc1    = (float*)p;
    cudaGetSymbolAddress(&p, g_bc2);    bc2    = (float*)p;
    cudaGetSymbolAddress(&p, g_src);    srcA   = (int*)p;
    cudaGetSymbolAddress(&p, g_dst);    dstA   = (int*)p;
    cudaGetSymbolAddress(&p, g_eidx);   eidx   = (int*)p;
    cudaGetSymbolAddress(&p, g_rowptr); rowptr = (int*)p;
    cudaGetSymbolAddress(&p, g_cnt);    cnt    = (int*)p;
    cudaGetSymbolAddress(&p, g_cur);    cur    = (int*)p;
    cudaGetSymbolAddress(&p, g_Zd);     Zd     = (double*)p;
    void* is64_p;
    cudaGetSymbolAddress(&is64_p, g_is64);

    const int eblocks = (E * 32 + 255) / 256;
    const int rowT256 = (N + 255) / 256;
    const int rowT128 = (N + 127) / 128;

    // main-stream prologue (launch #5 = l0 projection, profiled by ncu)
    cudaMemsetAsync(is64_p, 1, 4);                                      // 1
    int nsamp = E < 65536 ? E : 65536;
    detect_idx_k<<<(nsamp + 255) / 256, 256>>>(eiraw, nsamp);           // 2
    pack_w_k<<<2048, 256>>>(Wq, Wk, Wv, Wr, Whi, Whj, wpack);           // 3
    pack_b_k<<<(NL * 768 + 255) / 256, 256>>>(bq, bk, bv, br, bpack);   // 4

    // fork: side stream runs decode/CSR/compose concurrently with l0 proj
    cudaEventRecord(g_evF, 0);
    cudaStreamWaitEvent(g_s2, g_evF, 0);

    dim3 gproj256((6 * DH + 127) / 128, rowT256);
    mma_gemm_k<<<gproj256, 256>>>(N, 6 * DH, DIN, x_in, DIN,            // 5
                                  wpack, 768, bpack, qkv, 768, 0);

    // side stream
    decode_idx_k<<<512, 256, 0, g_s2>>>(E, N, eiraw, srcA, dstA);
    cudaMemsetAsync(cnt, 0, (size_t)N * sizeof(int), g_s2);
    cudaMemsetAsync(Zd, 0, NL * sizeof(double), g_s2);
    hist_k<<<512, 256, 0, g_s2>>>(E, dstA, cnt);
    scan_k<<<1, 1024, 0, g_s2>>>(N, cnt, rowptr, cur);
    scatter_k<<<512, 256, 0, g_s2>>>(E, dstA, cur, eidx);
    cudaMemsetAsync(wc1, 0, (size_t)DH * 768 * sizeof(float), g_s2);
    cudaMemsetAsync(wc2, 0, (size_t)DH * DH * sizeof(float), g_s2);
    {
        dim3 gc1(768 / 64, (DIN + 63) / 64);
        compose_w_k<<<gc1, 256, 0, g_s2>>>(linW, wpack + (size_t)DIN * 768, wc1, 768, DIN);
        dim3 gc2(DH / 64, (DIN + 63) / 64);
        compose_w_k<<<gc2, 256, 0, g_s2>>>(linW, lin2W, wc2, DH, DIN);
        compose_b_k<<<3, 256, 0, g_s2>>>(linb, wpack + (size_t)DIN * 768, bpack + 768,
                                         bc1, 768, DIN);
        compose_b_k<<<1, 128, 0, g_s2>>>(linb, lin2W, lin2b, bc2, DH, DIN);
    }
    cudaEventRecord(g_evJ, g_s2);
    cudaStreamWaitEvent(0, g_evJ, 0);

    for (int l = 0; l < NL; l++) {
        if (l > 0) {
            dim3 gp(6, rowT128);
            bm128_gemm_k<<<gp, 256>>>(N, 6 * DH, DH, h2, DH,
                                      wc1, 768, bc1, qkv, 768, 0,
                                      nullptr, nullptr, nullptr);
        }

        edge_score_k<<<eblocks, 256>>>(E, srcA, dstA, qkv, score, Zd + l);
        aggr_ln1_k<<<N, 128>>>(rowptr, eidx, srcA, qkv, eattr, score, Zd + l,
                               g1 + (size_t)l * DH, be1 + (size_t)l * DH, ss);

        dim3 gff1((DFF + 127) / 128, rowT128);
        bm128_gemm_k<<<gff1, 256>>>(N, DFF, DH, ss, DH,
                                    W1 + (size_t)l * DH * DFF, DFF,
                                    b1 + (size_t)l * DFF, tbuf, DFF, 1,
                                    nullptr, nullptr, nullptr);
        dim3 gff2(1, rowT128);
        bm128_gemm_k<<<gff2, 256>>>(N, DH, DFF, tbuf, DFF,
                                    W2 + (size_t)l * DFF * DH, DH,
                                    b2 + (size_t)l * DH, h2, DH, 0,
                                    ss, g2 + (size_t)l * DH, be2 + (size_t)l * DH);
    }

    dim3 gfin(1, rowT128);
    bm128_gemm_k<<<gfin, 256>>>(N, DH, DH, h2, DH, wc2, DH, bc2,
                                (float*)d_out, DH, 2,
                                nullptr, nullptr, nullptr);
}

// round 16
// speedup vs baseline: 1.7715x; 1.7715x over previous
#include <cuda_runtime.h>
#include <cuda_bf16.h>
#include <math.h>
#include <stdint.h>

#define DIN 1546
#define DH  128
#define DFF 512
#define NL  2

static const int NMAXC = 20000;
static const int EMAXC = 640000;

// ---------------- scratch (device globals; no allocation allowed) ----------
__device__ __align__(16) float g_qkv  [NMAXC * 6 * DH];
__device__ __align__(16) float g_scr  [EMAXC];
__device__ __align__(16) float g_ss   [NMAXC * DH];
__device__ __align__(16) float g_t    [NMAXC * DFF];
__device__ __align__(16) float g_h2   [NMAXC * DH];
__device__ __align__(16) float g_wpack[NL * DIN * 6 * DH];
__device__ __align__(16) float g_bpack[NL * 6 * DH];
__device__ __align__(16) float g_wc1  [DH * 6 * DH];
__device__ __align__(16) float g_wc2  [DH * DH];
__device__ __align__(16) float g_bc1  [6 * DH];
__device__ __align__(16) float g_bc2  [DH];
__device__ int g_src[EMAXC];
__device__ int g_dst[EMAXC];
__device__ int g_eidx[EMAXC];
__device__ int g_rowptr[NMAXC + 1];
__device__ int g_cnt[NMAXC];
__device__ int g_cur[NMAXC];
__device__ unsigned g_maxu2[NL];
__device__ float    g_Z2[NL];
__device__ int      g_is64;

__device__ __forceinline__ unsigned fenc(float f) {
    unsigned u = __float_as_uint(f);
    return (u & 0x80000000u) ? ~u : (u | 0x80000000u);
}
__device__ __forceinline__ float fdec(unsigned u) {
    return __uint_as_float((u & 0x80000000u) ? (u ^ 0x80000000u) : ~u);
}

// ---------------- bf16 split helpers ----------------------------------------
__device__ __forceinline__ uint32_t pack_bf2(__nv_bfloat16 a, __nv_bfloat16 b) {
    __nv_bfloat162 t = __halves2bfloat162(a, b);
    return *reinterpret_cast<uint32_t*>(&t);
}
__device__ __forceinline__ void split2(float x0, float x1, uint32_t& h, uint32_t& l) {
    __nv_bfloat16 h0 = __float2bfloat16(x0);
    __nv_bfloat16 h1 = __float2bfloat16(x1);
    __nv_bfloat16 l0 = __float2bfloat16(x0 - __bfloat162float(h0));
    __nv_bfloat16 l1 = __float2bfloat16(x1 - __bfloat162float(h1));
    h = pack_bf2(h0, h1);
    l = pack_bf2(l0, l1);
}
__device__ __forceinline__ void mma_bf16(float* c, const uint32_t* a, const uint32_t* b) {
    asm volatile(
        "mma.sync.aligned.m16n8k16.row.col.f32.bf16.bf16.f32 "
        "{%0,%1,%2,%3},{%4,%5,%6,%7},{%8,%9},{%0,%1,%2,%3};"
        : "+f"(c[0]), "+f"(c[1]), "+f"(c[2]), "+f"(c[3])
        : "r"(a[0]), "r"(a[1]), "r"(a[2]), "r"(a[3]), "r"(b[0]), "r"(b[1]));
}

// ---------------- edge-index dtype probe + decode ---------------------------
__global__ void detect_idx_k(const int* __restrict__ raw, int nsamp)
{
    int i = blockIdx.x * blockDim.x + threadIdx.x;
    if (i < nsamp && raw[2 * i + 1] != 0) atomicExch(&g_is64, 0);
}

__global__ void decode_idx_k(int E, int N, const int* __restrict__ raw,
                             int* __restrict__ src, int* __restrict__ dst)
{
    int is64 = g_is64;
    for (int e = blockIdx.x * blockDim.x + threadIdx.x; e < E;
         e += gridDim.x * blockDim.x) {
        int s, d;
        if (is64) {
            s = raw[2 * (size_t)e];
            d = raw[2 * ((size_t)E + e)];
        } else {
            s = raw[e];
            d = raw[(size_t)E + e];
        }
        src[e] = min(max(s, 0), N - 1);
        dst[e] = min(max(d, 0), N - 1);
    }
}

// ---------------- CSR build ---------------------------------------------------
__global__ void hist_k(int E, const int* __restrict__ dst, int* __restrict__ cnt)
{
    for (int e = blockIdx.x * blockDim.x + threadIdx.x; e < E;
         e += gridDim.x * blockDim.x)
        atomicAdd(&cnt[dst[e]], 1);
}

__global__ void scan_k(int N, const int* __restrict__ cnt,
                       int* __restrict__ rowptr, int* __restrict__ cur)
{
    __shared__ int part[1024];
    int t = threadIdx.x;
    int chunk = (N + 1023) / 1024;
    int lo = t * chunk, hi = min(lo + chunk, N);
    int s = 0;
    for (int j = lo; j < hi; j++) s += cnt[j];
    part[t] = s;
    __syncthreads();
    for (int off = 1; off < 1024; off <<= 1) {
        int v = (t >= off) ? part[t - off] : 0;
        __syncthreads();
        part[t] += v;
        __syncthreads();
    }
    int run = (t == 0) ? 0 : part[t - 1];
    for (int j = lo; j < hi; j++) {
        rowptr[j] = run;
        cur[j] = run;
        run += cnt[j];
    }
    if (t == 1023) rowptr[N] = part[1023];
}

__global__ void scatter_k(int E, const int* __restrict__ dst,
                          int* __restrict__ cur, int* __restrict__ eidx)
{
    for (int e = blockIdx.x * blockDim.x + threadIdx.x; e < E;
         e += gridDim.x * blockDim.x) {
        int pos = atomicAdd(&cur[dst[e]], 1);
        eidx[pos] = e;
    }
}

// ---------------- weight/bias packing (coalesced both sides) -----------------
__global__ void pack_w_k(const float* __restrict__ Wq, const float* __restrict__ Wk,
                         const float* __restrict__ Wv, const float* __restrict__ Wr,
                         const float* __restrict__ Whi, const float* __restrict__ Whj,
                         float* __restrict__ out)
{
    const float* Ws[6] = {Wq, Wk, Wv, Wr, Whi, Whj};
    size_t total = (size_t)NL * DIN * 768;
    for (size_t i = blockIdx.x * (size_t)blockDim.x + threadIdx.x; i < total;
         i += (size_t)gridDim.x * blockDim.x) {
        int n = i % 768;
        int k = (i / 768) % DIN;
        int l = i / ((size_t)768 * DIN);
        int j = n >> 7, c = n & 127;
        out[i] = Ws[j][(size_t)l * DIN * DH + (size_t)k * DH + c];
    }
}

__global__ void pack_b_k(const float* __restrict__ bq, const float* __restrict__ bk,
                         const float* __restrict__ bv, const float* __restrict__ br,
                         float* __restrict__ out)
{
    int i = threadIdx.x + blockIdx.x * blockDim.x;
    if (i >= NL * 768) return;
    int c = i % 768, l = i / 768;
    int j = c / DH, cc = c % DH;
    float v = 0.f;
    if (j == 0) v = bq[l * DH + cc];
    else if (j == 1) v = bk[l * DH + cc];
    else if (j == 2) v = bv[l * DH + cc];
    else if (j == 3) v = br[l * DH + cc];
    out[i] = v;
}

// ---------------- weight composition ------------------------------------------
__global__ void compose_w_k(const float* __restrict__ A, const float* __restrict__ B,
                            float* __restrict__ Cw, int No, int K)
{
    __shared__ float sA[128][65];
    const int tid = threadIdx.x;
    const int n    = tid & 63;
    const int mset = tid >> 6;
    const int nt0 = blockIdx.x * 64;
    const int k0  = blockIdx.y * 64;
    const int klen = min(64, K - k0);

    for (int id = tid; id < 128 * 64; id += 256) {
        int m = id >> 6, kk = id & 63;
        sA[m][kk] = (kk < klen) ? A[(size_t)m * K + k0 + kk] : 0.f;
    }
    __syncthreads();

    float acc[32];
#pragma unroll
    for (int i = 0; i < 32; i++) acc[i] = 0.f;

    for (int kk = 0; kk < klen; kk++) {
        float b = B[(size_t)(k0 + kk) * No + nt0 + n];
#pragma unroll
        for (int i = 0; i < 32; i++)
            acc[i] += sA[mset * 32 + i][kk] * b;
    }
#pragma unroll
    for (int i = 0; i < 32; i++)
        atomicAdd(&Cw[(size_t)(mset * 32 + i) * No + nt0 + n], acc[i]);
}

__global__ void compose_b_k(const float* __restrict__ lb, const float* __restrict__ B,
                            const float* __restrict__ badd, float* __restrict__ out,
                            int No, int K)
{
    int n = blockIdx.x * blockDim.x + threadIdx.x;
    if (n >= No) return;
    float s = badd ? badd[n] : 0.f;
    for (int k = 0; k < K; k++)
        s += lb[k] * B[(size_t)k * No + n];
    out[n] = s;
}

// ---------------- BM=256 tensor GEMM (proven; l0 proj K=1546) ----------------
__global__ void __launch_bounds__(256, 1)
mma_gemm_k(int M, int Nn, int K,
           const float* __restrict__ A, int lda,
           const float* __restrict__ B, int ldb,
           const float* __restrict__ bias,
           float* __restrict__ C, int ldc, int act)
{
    __shared__ __align__(16) uint32_t Asf[2][2][16][32][4];
    __shared__ __align__(16) uint32_t Bsf[2][2][16][32][2];

    const int tid  = threadIdx.x;
    const int lane = tid & 31;
    const int wid  = tid >> 5;
    const int g    = lane >> 2;
    const int tig  = lane & 3;
    const int warp_m = wid & 3;
    const int warp_n = wid >> 2;
    const int row0 = blockIdx.y * 256;
    const int col0 = blockIdx.x * 128;

    float acc[4][8][4];
#pragma unroll
    for (int m = 0; m < 4; m++)
#pragma unroll
        for (int n = 0; n < 8; n++)
#pragma unroll
            for (int r = 0; r < 4; r++) acc[m][n][r] = 0.f;

    float pa[2][8], pb[2][4];

    auto load_regs = [&](int k0) {
#pragma unroll
        for (int i = 0; i < 2; i++) {
            int mt = wid * 2 + i;
#pragma unroll
            for (int r = 0; r < 4; r++) {
                int rr = row0 + mt * 16 + g + 8 * (r & 1);
                int c0 = k0 + 2 * tig + 8 * (r >> 1);
                bool rok = rr < M;
                const float* Ap = A + (size_t)rr * lda + c0;
                pa[i][r * 2 + 0] = (rok && c0 < K)     ? Ap[0] : 0.f;
                pa[i][r * 2 + 1] = (rok && c0 + 1 < K) ? Ap[1] : 0.f;
            }
        }
#pragma unroll
        for (int i = 0; i < 2; i++) {
            int nt = wid * 2 + i;
            int cc = col0 + nt * 8 + g;
            bool cok = cc < Nn;
#pragma unroll
            for (int r = 0; r < 2; r++) {
                int kk = k0 + 2 * tig + 8 * r;
                pb[i][r * 2 + 0] = (cok && kk < K)     ? B[(size_t)kk * ldb + cc] : 0.f;
                pb[i][r * 2 + 1] = (cok && kk + 1 < K) ? B[(size_t)(kk + 1) * ldb + cc] : 0.f;
            }
        }
    };

    auto store_smem = [&](int buf) {
#pragma unroll
        for (int i = 0; i < 2; i++) {
            int mt = wid * 2 + i;
            uint4 h, l;
            split2(pa[i][0], pa[i][1], h.x, l.x);
            split2(pa[i][2], pa[i][3], h.y, l.y);
            split2(pa[i][4], pa[i][5], h.z, l.z);
            split2(pa[i][6], pa[i][7], h.w, l.w);
            *(uint4*)&Asf[buf][0][mt][lane][0] = h;
            *(uint4*)&Asf[buf][1][mt][lane][0] = l;
        }
#pragma unroll
        for (int i = 0; i < 2; i++) {
            int nt = wid * 2 + i;
            uint2 h, l;
            split2(pb[i][0], pb[i][1], h.x, l.x);
            split2(pb[i][2], pb[i][3], h.y, l.y);
            *(uint2*)&Bsf[buf][0][nt][lane][0] = h;
            *(uint2*)&Bsf[buf][1][nt][lane][0] = l;
        }
    };

    auto compute = [&](int buf) {
        uint32_t ah[4][4], al[4][4];
#pragma unroll
        for (int m = 0; m < 4; m++) {
            int mt = warp_m * 4 + m;
            uint4 t = *(const uint4*)&Asf[buf][0][mt][lane][0];
            ah[m][0] = t.x; ah[m][1] = t.y; ah[m][2] = t.z; ah[m][3] = t.w;
            uint4 u = *(const uint4*)&Asf[buf][1][mt][lane][0];
            al[m][0] = u.x; al[m][1] = u.y; al[m][2] = u.z; al[m][3] = u.w;
        }
#pragma unroll
        for (int n = 0; n < 8; n++) {
            int nt = warp_n * 8 + n;
            uint32_t bh[2], bl[2];
            uint2 t = *(const uint2*)&Bsf[buf][0][nt][lane][0];
            bh[0] = t.x; bh[1] = t.y;
            uint2 u = *(const uint2*)&Bsf[buf][1][nt][lane][0];
            bl[0] = u.x; bl[1] = u.y;
#pragma unroll
            for (int m = 0; m < 4; m++) {
                mma_bf16(acc[m][n], ah[m], bh);
                mma_bf16(acc[m][n], ah[m], bl);
                mma_bf16(acc[m][n], al[m], bh);
            }
        }
    };

    load_regs(0);
    store_smem(0);
    __syncthreads();

    int buf = 0;
    for (int k0 = 0; k0 < K; k0 += 16) {
        int kn = k0 + 16;
        bool more = kn < K;
        if (more) load_regs(kn);
        compute(buf);
        if (more) {
            store_smem(buf ^ 1);
            __syncthreads();
            buf ^= 1;
        }
    }

#pragma unroll
    for (int m = 0; m < 4; m++) {
        int rb = row0 + warp_m * 64 + m * 16 + g;
#pragma unroll
        for (int n = 0; n < 8; n++) {
            int cb = col0 + warp_n * 64 + n * 8 + tig * 2;
#pragma unroll
            for (int h = 0; h < 2; h++) {
                int rr = rb + h * 8;
                if (rr >= M) continue;
#pragma unroll
                for (int q = 0; q < 2; q++) {
                    int cc = cb + q;
                    if (cc >= Nn) continue;
                    float v = acc[m][n][h * 2 + q] + (bias ? bias[cc] : 0.f);
                    if (act == 1) v = fmaxf(v, 0.f);
                    else if (act == 2) v = v > 0.f ? v : 0.01f * v;
                    C[(size_t)rr * ldc + cc] = v;
                }
            }
        }
    }
}

// ---------------- BM=128 tensor GEMM, optional fused residual-LN epilogue ----
__global__ void __launch_bounds__(256, 1)
bm128_gemm_k(int M, int Nn, int K,
             const float* __restrict__ A, int lda,
             const float* __restrict__ B, int ldb,
             const float* __restrict__ bias,
             float* __restrict__ C, int ldc, int act,
             const float* __restrict__ lnres,
             const float* __restrict__ gam, const float* __restrict__ bet)
{
    __shared__ __align__(16) uint32_t Asf[2][2][8][32][4];
    __shared__ __align__(16) uint32_t Bsf[2][2][16][32][2];
    __shared__ float pS[2][128], pS2[2][128];

    const int tid  = threadIdx.x;
    const int lane = tid & 31;
    const int wid  = tid >> 5;
    const int g    = lane >> 2;
    const int tig  = lane & 3;
    const int warp_m = wid & 3;
    const int warp_n = wid >> 2;
    const int row0 = blockIdx.y * 128;
    const int col0 = blockIdx.x * 128;

    float acc[2][8][4];
#pragma unroll
    for (int m = 0; m < 2; m++)
#pragma unroll
        for (int n = 0; n < 8; n++)
#pragma unroll
            for (int r = 0; r < 4; r++) acc[m][n][r] = 0.f;

    float pa[8], pb[2][4];

    auto load_regs = [&](int k0) {
#pragma unroll
        for (int r = 0; r < 4; r++) {
            int rr = row0 + wid * 16 + g + 8 * (r & 1);
            int c0 = k0 + 2 * tig + 8 * (r >> 1);
            bool rok = rr < M;
            const float* Ap = A + (size_t)rr * lda + c0;
            pa[r * 2 + 0] = (rok && c0 < K)     ? Ap[0] : 0.f;
            pa[r * 2 + 1] = (rok && c0 + 1 < K) ? Ap[1] : 0.f;
        }
#pragma unroll
        for (int i = 0; i < 2; i++) {
            int nt = wid * 2 + i;
            int cc = col0 + nt * 8 + g;
            bool cok = cc < Nn;
#pragma unroll
            for (int r = 0; r < 2; r++) {
                int kk = k0 + 2 * tig + 8 * r;
                pb[i][r * 2 + 0] = (cok && kk < K)     ? B[(size_t)kk * ldb + cc] : 0.f;
                pb[i][r * 2 + 1] = (cok && kk + 1 < K) ? B[(size_t)(kk + 1) * ldb + cc] : 0.f;
            }
        }
    };

    auto store_smem = [&](int buf) {
        uint4 h, l;
        split2(pa[0], pa[1], h.x, l.x);
        split2(pa[2], pa[3], h.y, l.y);
        split2(pa[4], pa[5], h.z, l.z);
        split2(pa[6], pa[7], h.w, l.w);
        *(uint4*)&Asf[buf][0][wid][lane][0] = h;
        *(uint4*)&Asf[buf][1][wid][lane][0] = l;
#pragma unroll
        for (int i = 0; i < 2; i++) {
            int nt = wid * 2 + i;
            uint2 bh, bl;
            split2(pb[i][0], pb[i][1], bh.x, bl.x);
            split2(pb[i][2], pb[i][3], bh.y, bl.y);
            *(uint2*)&Bsf[buf][0][nt][lane][0] = bh;
            *(uint2*)&Bsf[buf][1][nt][lane][0] = bl;
        }
    };

    auto compute = [&](int buf) {
        uint32_t ah[2][4], al[2][4];
#pragma unroll
        for (int m = 0; m < 2; m++) {
            int mt = warp_m * 2 + m;
            uint4 t = *(const uint4*)&Asf[buf][0][mt][lane][0];
            ah[m][0] = t.x; ah[m][1] = t.y; ah[m][2] = t.z; ah[m][3] = t.w;
            uint4 u = *(const uint4*)&Asf[buf][1][mt][lane][0];
            al[m][0] = u.x; al[m][1] = u.y; al[m][2] = u.z; al[m][3] = u.w;
        }
#pragma unroll
        for (int n = 0; n < 8; n++) {
            int nt = warp_n * 8 + n;
            uint32_t bh[2], bl[2];
            uint2 t = *(const uint2*)&Bsf[buf][0][nt][lane][0];
            bh[0] = t.x; bh[1] = t.y;
            uint2 u = *(const uint2*)&Bsf[buf][1][nt][lane][0];
            bl[0] = u.x; bl[1] = u.y;
#pragma unroll
            for (int m = 0; m < 2; m++) {
                mma_bf16(acc[m][n], ah[m], bh);
                mma_bf16(acc[m][n], ah[m], bl);
                mma_bf16(acc[m][n], al[m], bh);
            }
        }
    };

    load_regs(0);
    store_smem(0);
    __syncthreads();

    int buf = 0;
    for (int k0 = 0; k0 < K; k0 += 16) {
        int kn = k0 + 16;
        bool more = kn < K;
        if (more) load_regs(kn);
        compute(buf);
        if (more) {
            store_smem(buf ^ 1);
            __syncthreads();
            buf ^= 1;
        }
    }

    if (gam == nullptr) {
#pragma unroll
        for (int m = 0; m < 2; m++) {
            int rb = row0 + warp_m * 32 + m * 16 + g;
#pragma unroll
            for (int n = 0; n < 8; n++) {
                int cb = col0 + warp_n * 64 + n * 8 + tig * 2;
#pragma unroll
                for (int h = 0; h < 2; h++) {
                    int rr = rb + h * 8;
                    if (rr >= M) continue;
#pragma unroll
                    for (int q = 0; q < 2; q++) {
                        int cc = cb + q;
                        if (cc >= Nn) continue;
                        float v = acc[m][n][h * 2 + q] + (bias ? bias[cc] : 0.f);
                        if (act == 1) v = fmaxf(v, 0.f);
                        else if (act == 2) v = v > 0.f ? v : 0.01f * v;
                        C[(size_t)rr * ldc + cc] = v;
                    }
                }
            }
        }
        return;
    }

    // fused residual-LN epilogue (Nn==128, col0==0)
    __syncthreads();
#pragma unroll
    for (int m = 0; m < 2; m++) {
#pragma unroll
        for (int h = 0; h < 2; h++) {
            int lrow = warp_m * 32 + m * 16 + g + 8 * h;
            int row  = row0 + lrow;
            bool rok = row < M;
            float rs = 0.f, rs2 = 0.f;
#pragma unroll
            for (int n = 0; n < 8; n++) {
#pragma unroll
                for (int q = 0; q < 2; q++) {
                    int col = warp_n * 64 + n * 8 + tig * 2 + q;
                    float v = acc[m][n][h * 2 + q] + bias[col]
                            + (rok ? lnres[(size_t)row * 128 + col] : 0.f);
                    rs += v; rs2 += v * v;
                }
            }
            rs  += __shfl_xor_sync(0xffffffffu, rs, 1);
            rs  += __shfl_xor_sync(0xffffffffu, rs, 2);
            rs2 += __shfl_xor_sync(0xffffffffu, rs2, 1);
            rs2 += __shfl_xor_sync(0xffffffffu, rs2, 2);
            if (tig == 0) { pS[warp_n][lrow] = rs; pS2[warp_n][lrow] = rs2; }
        }
    }
    __syncthreads();
#pragma unroll
    for (int m = 0; m < 2; m++) {
#pragma unroll
        for (int h = 0; h < 2; h++) {
            int lrow = warp_m * 32 + m * 16 + g + 8 * h;
            int row  = row0 + lrow;
            if (row >= M) continue;
            float ts  = pS[0][lrow] + pS[1][lrow];
            float ts2 = pS2[0][lrow] + pS2[1][lrow];
            float mean = ts * (1.f / 128.f);
            float var  = ts2 * (1.f / 128.f) - mean * mean;
            float rstd = rsqrtf(var + 1e-5f);
#pragma unroll
            for (int n = 0; n < 8; n++) {
#pragma unroll
                for (int q = 0; q < 2; q++) {
                    int col = warp_n * 64 + n * 8 + tig * 2 + q;
                    float v = acc[m][n][h * 2 + q] + bias[col]
                            + lnres[(size_t)row * 128 + col];
                    C[(size_t)row * ldc + col] = (v - mean) * rstd * gam[col] + bet[col];
                }
            }
        }
    }
}

// ---------------- edge pass 1: score + global max (fp32, r14 semantics) ------
__global__ void edge_score_k(int E, const int* __restrict__ srcA,
                             const int* __restrict__ dstA,
                             const float* __restrict__ qkv,
                             float* __restrict__ score,
                             unsigned* __restrict__ maxp)
{
    int warp  = (blockIdx.x * blockDim.x + threadIdx.x) >> 5;
    int lane  = threadIdx.x & 31;
    int wloc  = threadIdx.x >> 5;
    __shared__ float sm[8];
    float d = -3.4e38f;
    if (warp < E) {
        int src = srcA[warp];
        int dst = dstA[warp];
        float4 q = *(const float4*)(qkv + (size_t)dst * 768 + lane * 4);
        float4 k = *(const float4*)(qkv + (size_t)src * 768 + 128 + lane * 4);
        d = q.x * k.x + q.y * k.y + q.z * k.z + q.w * k.w;
#pragma unroll
        for (int o = 16; o; o >>= 1) d += __shfl_xor_sync(0xffffffffu, d, o);
        if (lane == 0) score[warp] = d;
    }
    if (lane == 0) sm[wloc] = d;
    __syncthreads();
    if (threadIdx.x == 0) {
        float m = sm[0];
        int nw = blockDim.x >> 5;
        for (int i = 1; i < nw; i++) m = fmaxf(m, sm[i]);
        atomicMax(maxp, fenc(m));
    }
}

// ---------------- edge pass 2: p = exp(s-max); Z = sum ------------------------
__global__ void expsum_k(int E, float* __restrict__ score,
                         const unsigned* __restrict__ maxp,
                         float* __restrict__ Zp)
{
    float gmax = fdec(*maxp);
    float s = 0.f;
    for (int i = blockIdx.x * blockDim.x + threadIdx.x; i < E;
         i += gridDim.x * blockDim.x) {
        float p = __expf(score[i] - gmax);   // arg <= 0: fast exp is safe
        score[i] = p;
        s += p;
    }
#pragma unroll
    for (int o = 16; o; o >>= 1) s += __shfl_xor_sync(0xffffffffu, s, o);
    __shared__ float sm[8];
    int w = threadIdx.x >> 5, l = threadIdx.x & 31;
    if (l == 0) sm[w] = s;
    __syncthreads();
    if (threadIdx.x == 0) {
        float t = 0.f;
        int nw = blockDim.x >> 5;
        for (int i = 0; i < nw; i++) t += sm[i];
        atomicAdd(Zp, t);
    }
}

// ---------------- fused aggregate + LN1 (fast-math sigmoid) -------------------
__global__ void __launch_bounds__(128)
aggr_ln1_k(const int* __restrict__ rowptr, const int* __restrict__ eidx,
           const int* __restrict__ srcA,
           const float* __restrict__ qkv, const float* __restrict__ eattr,
           const float* __restrict__ score,
           const float* __restrict__ Zp,
           const float* __restrict__ gam, const float* __restrict__ bet,
           float* __restrict__ out)
{
    int n = blockIdx.x, d = threadIdx.x;
    int beg = rowptr[n], end = rowptr[n + 1];
    float hj = qkv[(size_t)n * 768 + 640 + d];
    float acc = 0.f;

    int i = beg;
    for (; i + 3 < end; i += 4) {
        int e0 = eidx[i], e1 = eidx[i + 1], e2 = eidx[i + 2], e3 = eidx[i + 3];
        int s0 = srcA[e0], s1 = srcA[e1], s2 = srcA[e2], s3 = srcA[e3];
        float p0 = __ldg(score + e0), p1 = __ldg(score + e1);
        float p2 = __ldg(score + e2), p3 = __ldg(score + e3);
        float v0  = qkv[(size_t)s0 * 768 + 256 + d];
        float v1  = qkv[(size_t)s1 * 768 + 256 + d];
        float v2  = qkv[(size_t)s2 * 768 + 256 + d];
        float v3  = qkv[(size_t)s3 * 768 + 256 + d];
        float hi0 = qkv[(size_t)s0 * 768 + 512 + d];
        float hi1 = qkv[(size_t)s1 * 768 + 512 + d];
        float hi2 = qkv[(size_t)s2 * 768 + 512 + d];
        float hi3 = qkv[(size_t)s3 * 768 + 512 + d];
        float ea0 = eattr[(size_t)e0 * 128 + d];
        float ea1 = eattr[(size_t)e1 * 128 + d];
        float ea2 = eattr[(size_t)e2 * 128 + d];
        float ea3 = eattr[(size_t)e3 * 128 + d];
        acc += p0 * v0 * __fdividef(1.f, 1.f + __expf(-(ea0 + hi0 + hj)));
        acc += p1 * v1 * __fdividef(1.f, 1.f + __expf(-(ea1 + hi1 + hj)));
        acc += p2 * v2 * __fdividef(1.f, 1.f + __expf(-(ea2 + hi2 + hj)));
        acc += p3 * v3 * __fdividef(1.f, 1.f + __expf(-(ea3 + hi3 + hj)));
    }
    for (; i < end; i++) {
        int e0 = eidx[i];
        int s0 = srcA[e0];
        float p0 = __ldg(score + e0);
        float v0  = qkv[(size_t)s0 * 768 + 256 + d];
        float hi0 = qkv[(size_t)s0 * 768 + 512 + d];
        float ea0 = eattr[(size_t)e0 * 128 + d];
        acc += p0 * v0 * __fdividef(1.f, 1.f + __expf(-(ea0 + hi0 + hj)));
    }

    float h = acc / (*Zp) + qkv[(size_t)n * 768 + 384 + d];

    float s = h, s2 = h * h;
#pragma unroll
    for (int o = 16; o; o >>= 1) {
        s  += __shfl_xor_sync(0xffffffffu, s, o);
        s2 += __shfl_xor_sync(0xffffffffu, s2, o);
    }
    __shared__ float sm[8];
    int w = threadIdx.x >> 5, l = threadIdx.x & 31;
    if (l == 0) { sm[w] = s; sm[4 + w] = s2; }
    __syncthreads();
    float ts  = sm[0] + sm[1] + sm[2] + sm[3];
    float ts2 = sm[4] + sm[5] + sm[6] + sm[7];
    float mean = ts * (1.f / 128.f);
    float var  = ts2 * (1.f / 128.f) - mean * mean;
    out[(size_t)n * 128 + d] = (h - mean) * rsqrtf(var + 1e-5f) * gam[d] + bet[d];
}

// ---------------- host-side persistent stream/events -------------------------
static cudaStream_t g_s2 = nullptr;
static cudaEvent_t  g_evF = nullptr, g_evJ = nullptr;

// ---------------- host orchestration ---------------------------------------
extern "C" void kernel_launch(void* const* d_in, const int* in_sizes, int n_in,
                              void* d_out, int out_size)
{
    const float* x_in  = (const float*)d_in[0];
    const int*   eiraw = (const int*)d_in[1];
    const float* eattr = (const float*)d_in[2];
    const float* Wq  = (const float*)d_in[3];
    const float* bq  = (const float*)d_in[4];
    const float* Wk  = (const float*)d_in[5];
    const float* bk  = (const float*)d_in[6];
    const float* Wv  = (const float*)d_in[7];
    const float* bv  = (const float*)d_in[8];
    const float* Wr  = (const float*)d_in[9];
    const float* br  = (const float*)d_in[10];
    const float* Whi = (const float*)d_in[11];
    const float* Whj = (const float*)d_in[12];
    const float* W1  = (const float*)d_in[13];
    const float* b1  = (const float*)d_in[14];
    const float* W2  = (const float*)d_in[15];
    const float* b2  = (const float*)d_in[16];
    const float* g1  = (const float*)d_in[17];
    const float* be1 = (const float*)d_in[18];
    const float* g2  = (const float*)d_in[19];
    const float* be2 = (const float*)d_in[20];
    const float* linW  = (const float*)d_in[21];
    const float* linb  = (const float*)d_in[22];
    const float* lin2W = (const float*)d_in[23];
    const float* lin2b = (const float*)d_in[24];

    const int N = in_sizes[0] / DIN;
    const int E = in_sizes[1] / 2;

    if (!g_s2) {
        cudaStreamCreateWithFlags(&g_s2, cudaStreamNonBlocking);
        cudaEventCreateWithFlags(&g_evF, cudaEventDisableTiming);
        cudaEventCreateWithFlags(&g_evJ, cudaEventDisableTiming);
    }

    float *qkv, *score, *ss, *tbuf, *h2, *wpack, *bpack;
    float *wc1, *wc2, *bc1, *bc2, *Zarr;
    unsigned* maxarr;
    int *srcA, *dstA, *eidx, *rowptr, *cnt, *cur;
    void* p;
    cudaGetSymbolAddress(&p, g_qkv);    qkv    = (float*)p;
    cudaGetSymbolAddress(&p, g_scr);    score  = (float*)p;
    cudaGetSymbolAddress(&p, g_ss);     ss     = (float*)p;
    cudaGetSymbolAddress(&p, g_t);      tbuf   = (float*)p;
    cudaGetSymbolAddress(&p, g_h2);     h2     = (float*)p;
    cudaGetSymbolAddress(&p, g_wpack);  wpack  = (float*)p;
    cudaGetSymbolAddress(&p, g_bpack);  bpack  = (float*)p;
    cudaGetSymbolAddress(&p, g_wc1);    wc1    = (float*)p;
    cudaGetSymbolAddress(&p, g_wc2);    wc2    = (float*)p;
    cudaGetSymbolAddress(&p, g_bc1);    bc1    = (float*)p;
    cudaGetSymbolAddress(&p, g_bc2);    bc2    = (float*)p;
    cudaGetSymbolAddress(&p, g_src);    srcA   = (int*)p;
    cudaGetSymbolAddress(&p, g_dst);    dstA   = (int*)p;
    cudaGetSymbolAddress(&p, g_eidx);   eidx   = (int*)p;
    cudaGetSymbolAddress(&p, g_rowptr); rowptr = (int*)p;
    cudaGetSymbolAddress(&p, g_cnt);    cnt    = (int*)p;
    cudaGetSymbolAddress(&p, g_cur);    cur    = (int*)p;
    cudaGetSymbolAddress(&p, g_maxu2);  maxarr = (unsigned*)p;
    cudaGetSymbolAddress(&p, g_Z2);     Zarr   = (float*)p;
    void* is64_p;
    cudaGetSymbolAddress(&is64_p, g_is64);

    const int eblocks = (E * 32 + 255) / 256;
    const int rowT256 = (N + 255) / 256;
    const int rowT128 = (N + 127) / 128;

    // main-stream prologue (launch #5 = l0 projection, profiled by ncu)
    cudaMemsetAsync(is64_p, 1, 4);                                      // 1
    int nsamp = E < 65536 ? E : 65536;
    detect_idx_k<<<(nsamp + 255) / 256, 256>>>(eiraw, nsamp);           // 2
    pack_w_k<<<2048, 256>>>(Wq, Wk, Wv, Wr, Whi, Whj, wpack);           // 3
    pack_b_k<<<(NL * 768 + 255) / 256, 256>>>(bq, bk, bv, br, bpack);   // 4

    // fork: side stream runs decode/CSR/compose concurrently with l0 proj
    cudaEventRecord(g_evF, 0);
    cudaStreamWaitEvent(g_s2, g_evF, 0);

    dim3 gproj256((6 * DH + 127) / 128, rowT256);
    mma_gemm_k<<<gproj256, 256>>>(N, 6 * DH, DIN, x_in, DIN,            // 5
                                  wpack, 768, bpack, qkv, 768, 0);

    // side stream
    decode_idx_k<<<512, 256, 0, g_s2>>>(E, N, eiraw, srcA, dstA);
    cudaMemsetAsync(cnt, 0, (size_t)N * sizeof(int), g_s2);
    cudaMemsetAsync(maxarr, 0, NL * sizeof(unsigned), g_s2);
    cudaMemsetAsync(Zarr, 0, NL * sizeof(float), g_s2);
    hist_k<<<512, 256, 0, g_s2>>>(E, dstA, cnt);
    scan_k<<<1, 1024, 0, g_s2>>>(N, cnt, rowptr, cur);
    scatter_k<<<512, 256, 0, g_s2>>>(E, dstA, cur, eidx);
    cudaMemsetAsync(wc1, 0, (size_t)DH * 768 * sizeof(float), g_s2);
    cudaMemsetAsync(wc2, 0, (size_t)DH * DH * sizeof(float), g_s2);
    {
        dim3 gc1(768 / 64, (DIN + 63) / 64);
        compose_w_k<<<gc1, 256, 0, g_s2>>>(linW, wpack + (size_t)DIN * 768, wc1, 768, DIN);
        dim3 gc2(DH / 64, (DIN + 63) / 64);
        compose_w_k<<<gc2, 256, 0, g_s2>>>(linW, lin2W, wc2, DH, DIN);
        compose_b_k<<<3, 256, 0, g_s2>>>(linb, wpack + (size_t)DIN * 768, bpack + 768,
                                         bc1, 768, DIN);
        compose_b_k<<<1, 128, 0, g_s2>>>(linb, lin2W, lin2b, bc2, DH, DIN);
    }
    cudaEventRecord(g_evJ, g_s2);
    cudaStreamWaitEvent(0, g_evJ, 0);

    for (int l = 0; l < NL; l++) {
        if (l > 0) {
            dim3 gp(6, rowT128);
            bm128_gemm_k<<<gp, 256>>>(N, 6 * DH, DH, h2, DH,
                                      wc1, 768, bc1, qkv, 768, 0,
                                      nullptr, nullptr, nullptr);
        }

        edge_score_k<<<eblocks, 256>>>(E, srcA, dstA, qkv, score, maxarr + l);
        expsum_k<<<1024, 256>>>(E, score, maxarr + l, Zarr + l);
        aggr_ln1_k<<<N, 128>>>(rowptr, eidx, srcA, qkv, eattr, score, Zarr + l,
                               g1 + (size_t)l * DH, be1 + (size_t)l * DH, ss);

        dim3 gff1((DFF + 127) / 128, rowT128);
        bm128_gemm_k<<<gff1, 256>>>(N, DFF, DH, ss, DH,
                                    W1 + (size_t)l * DH * DFF, DFF,
                                    b1 + (size_t)l * DFF, tbuf, DFF, 1,
                                    nullptr, nullptr, nullptr);
        dim3 gff2(1, rowT128);
        bm128_gemm_k<<<gff2, 256>>>(N, DH, DFF, tbuf, DFF,
                                    W2 + (size_t)l * DFF * DH, DH,
                                    b2 + (size_t)l * DH, h2, DH, 0,
                                    ss, g2 + (size_t)l * DH, be2 + (size_t)l * DH);
    }

    dim3 gfin(1, rowT128);
    bm128_gemm_k<<<gfin, 256>>>(N, DH, DH, h2, DH, wc2, DH, bc2,
                                (float*)d_out, DH, 2,
                                nullptr, nullptr, nullptr);
}